// round 17
// baseline (speedup 1.0000x reference)
#include <cuda_runtime.h>
#include <cuda_bf16.h>
#include <cstdint>

#define FULLMASK 0xffffffffu

// ---------------------------------------------------------------------------
// Codegen model (validated R10/R13/R14/R16):
//  - lone ternary `p ? fmaxf : fminf`  -> 1 predicated FMNMX (alu pipe)
//  - two ternaries over the SAME pair  -> CSE degrades to FMNMX+FMNMX+SEL+SEL
//  - FADD/FFMA are steered across both FP pipes; FMNMX is alu-only
//  - kernel is issue-slot bound => minimize issued instructions
// ---------------------------------------------------------------------------

// Scalar runtime-direction CE: 1 alu + 2 flex, 3 issue slots, no SELs.
// down == true -> a (lower index) keeps MAX (descending).
__device__ __forceinline__ void ce_a1(float& a, float& b, bool down) {
    float s  = a + b;                              // FADD
    float lo = down ? fminf(a, b) : fmaxf(a, b);   // FMNMX P
    a = s - lo;                                    // FADD
    b = lo;
}

// ---- Packed helpers (Blackwell f32x2) -------------------------------------
__device__ __forceinline__ unsigned long long pk2(float lo, float hi) {
    unsigned long long r;
    asm("mov.b64 %0, {%1, %2};" : "=l"(r) : "f"(lo), "f"(hi));
    return r;
}
__device__ __forceinline__ void upk2(unsigned long long p, float& lo, float& hi) {
    asm("mov.b64 {%0, %1}, %2;" : "=f"(lo), "=f"(hi) : "l"(p));
}

// Paired runtime-direction CE on (a0,b0) and (a1,b1), same direction.
// 2 CEs in 4 instructions: ADD.f32x2 + 2x predicated FMNMX + FMA.f32x2(x -1).
// (a0,a1) and (b0,b1) are adjacent even-aligned v[] elements, so the
// mov.b64 packs/unpacks collapse into register-pair allocation.
__device__ __forceinline__ void ce_a2(float& a0, float& a1,
                                      float& b0, float& b1, bool down) {
    unsigned long long A = pk2(a0, a1);
    unsigned long long B = pk2(b0, b1);
    unsigned long long S;
    asm("add.rn.f32x2 %0, %1, %2;" : "=l"(S) : "l"(A), "l"(B));
    float lo0 = down ? fminf(a0, b0) : fmaxf(a0, b0);   // FMNMX P
    float lo1 = down ? fminf(a1, b1) : fmaxf(a1, b1);   // FMNMX P
    unsigned long long L = pk2(lo0, lo1);
    const unsigned long long M1 = 0xBF800000BF800000ULL; // packed (-1.f,-1.f)
    unsigned long long H;
    asm("fma.rn.f32x2 %0, %1, %2, %3;" : "=l"(H) : "l"(L), "l"(M1), "l"(S));
    upk2(H, a0, a1);
    b0 = lo0; b1 = lo1;
}

// ---------------------------------------------------------------------------
// Phase 1: Batcher odd-even mergesort of the 32 in-register values
// (191 comparators), runtime per-lane direction via ce_a1.
// ---------------------------------------------------------------------------
template<int LO, int N, int R>
__device__ __forceinline__ void oem_merge(float (&v)[32], bool down) {
    constexpr int M = 2 * R;
    if constexpr (M < N) {
        oem_merge<LO,     N, M>(v, down);
        oem_merge<LO + R, N, M>(v, down);
        #pragma unroll
        for (int i = LO + R; i + R < LO + N; i += M)
            ce_a1(v[i], v[i + R], down);
    } else {
        ce_a1(v[LO], v[LO + R], down);
    }
}

template<int LO, int N>
__device__ __forceinline__ void oem_sort(float (&v)[32], bool down) {
    if constexpr (N > 1) {
        oem_sort<LO,         N / 2>(v, down);
        oem_sort<LO + N / 2, N / 2>(v, down);
        oem_merge<LO, N, 1>(v, down);
    }
}

// ---------------------------------------------------------------------------
// Phase 2: bitonic merge stages K = 64 .. 1024 across lanes.
// idx = lane*32 + r; direction bit (idx & K) is a lane bit, uniform per pass.
// ---------------------------------------------------------------------------

// Runtime-direction in-register pass (stages K=64..512).
template<int K, int J>
__device__ __forceinline__ void pass_reg_rt(float (&v)[32], int lane) {
    const bool down = ((lane & (K >> 5)) == 0);
    if constexpr (J >= 2) {
        #pragma unroll
        for (int r = 0; r < 32; r += 2)
            if ((r & J) == 0)
                ce_a2(v[r], v[r + 1], v[r | J], v[(r | J) + 1], down);
    } else {
        #pragma unroll
        for (int r = 0; r < 32; r += 2)
            ce_a1(v[r], v[r + 1], down);
    }
}

// Compile-time descending pass (final stage K=1024: lane & 32 == 0 always).
// Plain fminf/fmaxf -> 2 non-predicated FMNMX, no CSE hazard.
template<int J>
__device__ __forceinline__ void pass_reg_desc(float (&v)[32]) {
    #pragma unroll
    for (int r = 0; r < 32; r++)
        if ((r & J) == 0) {
            float hi = fmaxf(v[r], v[r | J]);
            float lo = fminf(v[r], v[r | J]);
            v[r] = hi; v[r | J] = lo;
        }
}

// Cross-lane pass: 1 SHFL + 1 lone-ternary predicated FMNMX per element.
template<int K, int J>
__device__ __forceinline__ void pass_shfl(float (&v)[32], int lane) {
    constexpr int MASK = J >> 5;
    const bool down     = ((lane & (K >> 5)) == 0);
    const bool keep_max = (down == ((lane & MASK) == 0));
    #pragma unroll
    for (int r = 0; r < 32; r++) {
        float p = __shfl_xor_sync(FULLMASK, v[r], MASK);
        v[r] = keep_max ? fmaxf(v[r], p) : fminf(v[r], p);
    }
}

template<int K, int J>
__device__ __forceinline__ void merge_steps(float (&v)[32], int lane) {
    if constexpr (J >= 32)       pass_shfl<K, J>(v, lane);
    else if constexpr (K == 1024) pass_reg_desc<J>(v);
    else                          pass_reg_rt<K, J>(v, lane);
    if constexpr (J > 1) merge_steps<K, (J >> 1)>(v, lane);
}

template<int K>
__device__ __forceinline__ void bitonic_stage(float (&v)[32], int lane) {
    merge_steps<K, (K >> 1)>(v, lane);
    if constexpr (K < 1024) bitonic_stage<(K << 1)>(v, lane);
}

// ---------------------------------------------------------------------------
// Kernel: one warp per row. 128-thread blocks + launch_bounds(128, 9):
// at the 56-reg cap this packs 36 warps/SM (vs 32 with 256-thr blocks),
// trimming the occupancy quantization loss.
// ---------------------------------------------------------------------------
__global__ void __launch_bounds__(128, 9)
GlobalRankPooling_kernel(const float* __restrict__ x,
                         const float* __restrict__ w,
                         const float* __restrict__ bias,
                         float* __restrict__ out,
                         int C, int rows) {
    const int lane = threadIdx.x & 31;
    const int row  = blockIdx.x * (blockDim.x >> 5) + (threadIdx.x >> 5);
    if (row >= rows) return;
    const int c = row & (C - 1);   // C = 2048 (power of two)

    // ---- Load: fully coalesced float4. Initial placement is irrelevant.
    float v[32];
    const float4* xp = reinterpret_cast<const float4*>(x) + (size_t)row * 256;
    #pragma unroll
    for (int i = 0; i < 8; i++) {
        float4 t = xp[i * 32 + lane];
        v[4 * i + 0] = t.x; v[4 * i + 1] = t.y;
        v[4 * i + 2] = t.z; v[4 * i + 3] = t.w;
    }

    // ---- Phase 1: per-lane 32-element Batcher sort (191 CEs).
    // Even lanes descending, odd ascending -> bitonic-stage-32 post-state.
    oem_sort<0, 32>(v, (lane & 1) == 0);

    // ---- Phase 2: cross-lane bitonic merges K=64..1024 (descending).
    bitonic_stage<64>(v, lane);
    // Now v[r] on `lane` = sorted_desc[lane*32 + r].

    // ---- Dot with weight row in sorted-rank order; w stays L2-resident.
    const float4* wp = reinterpret_cast<const float4*>(w) + (size_t)c * 256 + lane * 8;
    float acc = 0.0f;
    #pragma unroll
    for (int i = 0; i < 8; i++) {
        float4 t = wp[i];
        acc = fmaf(t.x, v[4 * i + 0], acc);
        acc = fmaf(t.y, v[4 * i + 1], acc);
        acc = fmaf(t.z, v[4 * i + 2], acc);
        acc = fmaf(t.w, v[4 * i + 3], acc);
    }

    // ---- Warp reduce + bias.
    #pragma unroll
    for (int m = 16; m; m >>= 1) acc += __shfl_xor_sync(FULLMASK, acc, m);
    if (lane == 0) out[row] = acc + __ldg(bias + c);
}

extern "C" void kernel_launch(void* const* d_in, const int* in_sizes, int n_in,
                              void* d_out, int out_size) {
    const float* x    = (const float*)d_in[0];   // (B, C, H, W) fp32
    const float* w    = (const float*)d_in[1];   // (C, 1, S)    fp32
    const float* bias = (const float*)d_in[2];   // (C,)         fp32
    float* out = (float*)d_out;                  // (B, C, 1)    fp32

    const int C    = in_sizes[2];                // 2048
    const int rows = in_sizes[0] / 1024;         // B*C = 65536 (S = 1024)

    const int warps_per_block = 4;               // 128 threads
    const int blocks = (rows + warps_per_block - 1) / warps_per_block;
    GlobalRankPooling_kernel<<<blocks, 128>>>(x, w, bias, out, C, rows);
}